// round 1
// baseline (speedup 1.0000x reference)
#include <cuda_runtime.h>
#include <math.h>

#define Bv   16384
#define Tv   60
#define Hv   128
#define NXv  4
#define NXSv 3
#define NYv  4
#define NYSv 3

// ---------------- scratch (__device__ globals; no allocations allowed) ----------------
__device__ float g_r1[(size_t)Tv * Bv * Hv];   // layer1 outputs, stored time-reversed: [T][B][H]
__device__ float g_r2[(size_t)Tv * Bv * Hv];   // layer2 outputs: [T][B][H]
__device__ float g_h1[Bv * Hv];                // layer1 initial h
__device__ float g_c1[Bv * Hv];                // layer1 c state (in-place)
__device__ float g_c2[Bv * Hv];                // layer2 c state (in-place)
__device__ float g_b1[4 * Hv];                 // bih1 + bhh1
__device__ float g_b2[4 * Hv];                 // bih2 + bhh2
__device__ float g_wcomb[NYv * Hv];            // Wout @ Wlat   [4,128]
__device__ float g_bcomb[NYv];                 // Wout @ blat + bout

__device__ __forceinline__ float sigmoidf_(float x) { return 1.0f / (1.0f + expf(-x)); }

// ---------------- init: h0/c0 for layer1 from sfc inputs; copy c2 ----------------
__global__ void init_kernel(const float* __restrict__ sfc,
                            const float* __restrict__ Ws1, const float* __restrict__ bs1,
                            const float* __restrict__ Ws2, const float* __restrict__ bs2,
                            const float* __restrict__ cx2)
{
    int i = blockIdx.x * blockDim.x + threadIdx.x;
    if (i >= Bv * Hv) return;
    int b = i >> 7, j = i & 127;
    float s0 = sfc[b * 3 + 0], s1 = sfc[b * 3 + 1], s2 = sfc[b * 3 + 2];
    float a1 = bs1[j] + s0 * Ws1[j * 3 + 0] + s1 * Ws1[j * 3 + 1] + s2 * Ws1[j * 3 + 2];
    float a2 = bs2[j] + s0 * Ws2[j * 3 + 0] + s1 * Ws2[j * 3 + 1] + s2 * Ws2[j * 3 + 2];
    g_h1[i] = tanhf(a1);
    g_c1[i] = tanhf(a2);
    g_c2[i] = cx2[i];
}

// ---------------- prep: combined biases + folded output projection ----------------
__global__ void prep_kernel(const float* __restrict__ bih1, const float* __restrict__ bhh1,
                            const float* __restrict__ bih2, const float* __restrict__ bhh2,
                            const float* __restrict__ Wlat, const float* __restrict__ blat,
                            const float* __restrict__ Wout, const float* __restrict__ bout)
{
    int i = blockIdx.x * blockDim.x + threadIdx.x;  // 512 threads
    if (i >= 512) return;
    g_b1[i] = bih1[i] + bhh1[i];
    g_b2[i] = bih2[i] + bhh2[i];
    int y = i >> 7, j = i & 127;
    float acc = 0.0f;
    for (int k = 0; k < Hv; k++) acc += Wout[y * Hv + k] * Wlat[k * Hv + j];
    g_wcomb[i] = acc;
    if (i < NYv) {
        float bb = bout[i];
        for (int k = 0; k < Hv; k++) bb += Wout[i * Hv + k] * blat[k];
        g_bcomb[i] = bb;
    }
}

// ---------------- fused LSTM step: Z = [x|m|h] @ W^T + b, then cell update ----------------
// Block: 128 samples (blockIdx.x) x 32 hidden units (blockIdx.y), all 4 gates.
// 256 threads, 8x8 microtile per thread. Column mapping n = tx + 16*j:
//   q = (n>>4)&3 (gate), u = n>>6, jj = u*16 + (n&15)  -> gate row g = q*128 + j0 + jj.
// Thread tx owns hiddens (j0+tx) and (j0+16+tx) with all 4 gates -> local cell update.
__global__ __launch_bounds__(256) void lstm_step(
    const float* __restrict__ xsrc, int xk, int xstride,   // optional x part (layer1: 4 feats)
    const float* __restrict__ msrc, int mstride,           // [B,128] "memory/input" slab
    const float* __restrict__ hin,                         // [B,128] previous h (stride 128)
    float* __restrict__ c,                                 // [B,128] c state in/out
    const float* __restrict__ Wih, int Kw,                 // [512, Kw]
    const float* __restrict__ Whh,                         // [512, 128]
    const float* __restrict__ bias,                        // [512] combined
    float* __restrict__ hstore)                            // [B,128] new h (also next hin)
{
    __shared__ float as[32][129];
    __shared__ float ws[32][129];
    const int tid = threadIdx.x;
    const int tx = tid & 15;
    const int ty = tid >> 4;
    const int b0 = blockIdx.x * 128;
    const int j0 = blockIdx.y * 32;

    float acc[8][8];
#pragma unroll
    for (int i = 0; i < 8; i++)
#pragma unroll
        for (int j = 0; j < 8; j++) acc[i][j] = 0.0f;

    for (int kc = 0; kc < 8; kc++) {
        const float* src; int soff, sstride; const float* wb; int wK, wcol;
        if (kc < 4) { src = msrc; soff = kc * 32;      sstride = mstride; wb = Wih; wK = Kw; wcol = xk + kc * 32; }
        else        { src = hin;  soff = (kc - 4) * 32; sstride = Hv;     wb = Whh; wK = Hv; wcol = (kc - 4) * 32; }
        __syncthreads();
#pragma unroll
        for (int p = 0; p < 16; p++) {
            int idx = tid + p * 256;
            int kk = idx & 31, bb = idx >> 5;
            as[kk][bb] = src[(size_t)(b0 + bb) * sstride + soff + kk];
        }
#pragma unroll
        for (int p = 0; p < 16; p++) {
            int idx = tid + p * 256;
            int kk = idx & 31, n = idx >> 5;
            int q = (n >> 4) & 3, u = n >> 6, jj = (u << 4) + (n & 15);
            int g = q * Hv + j0 + jj;
            ws[kk][n] = wb[(size_t)g * wK + wcol + kk];
        }
        __syncthreads();
#pragma unroll 8
        for (int kk = 0; kk < 32; kk++) {
            float a[8], w[8];
#pragma unroll
            for (int i = 0; i < 8; i++) a[i] = as[kk][ty * 8 + i];
#pragma unroll
            for (int j = 0; j < 8; j++) w[j] = ws[kk][tx + 16 * j];
#pragma unroll
            for (int i = 0; i < 8; i++)
#pragma unroll
                for (int j = 0; j < 8; j++) acc[i][j] += a[i] * w[j];
        }
    }

    if (xk > 0) {  // layer1's 4 raw input features (Wih columns 0..3)
        __syncthreads();
#pragma unroll
        for (int p = 0; p < 2; p++) {
            int idx = tid + p * 256;
            int kk = idx & 3, bb = idx >> 2;
            as[kk][bb] = xsrc[(size_t)(b0 + bb) * xstride + kk];
        }
#pragma unroll
        for (int p = 0; p < 2; p++) {
            int idx = tid + p * 256;
            int kk = idx & 3, n = idx >> 2;
            int q = (n >> 4) & 3, u = n >> 6, jj = (u << 4) + (n & 15);
            int g = q * Hv + j0 + jj;
            ws[kk][n] = Wih[(size_t)g * Kw + kk];
        }
        __syncthreads();
#pragma unroll
        for (int kk = 0; kk < 4; kk++) {
            float a[8], w[8];
#pragma unroll
            for (int i = 0; i < 8; i++) a[i] = as[kk][ty * 8 + i];
#pragma unroll
            for (int j = 0; j < 8; j++) w[j] = ws[kk][tx + 16 * j];
#pragma unroll
            for (int i = 0; i < 8; i++)
#pragma unroll
                for (int j = 0; j < 8; j++) acc[i][j] += a[i] * w[j];
        }
    }

    // ---- LSTM cell epilogue: thread owns all 4 gates of 2 hidden units x 8 samples ----
#pragma unroll
    for (int i = 0; i < 8; i++) {
        int bG = b0 + ty * 8 + i;
#pragma unroll
        for (int u = 0; u < 2; u++) {
            int jg = j0 + u * 16 + tx;
            float zi = acc[i][u * 4 + 0] + bias[0 * Hv + jg];
            float zf = acc[i][u * 4 + 1] + bias[1 * Hv + jg];
            float zg = acc[i][u * 4 + 2] + bias[2 * Hv + jg];
            float zo = acc[i][u * 4 + 3] + bias[3 * Hv + jg];
            size_t ci = (size_t)bG * Hv + jg;
            float cn = sigmoidf_(zf) * c[ci] + sigmoidf_(zi) * tanhf(zg);
            float hn = sigmoidf_(zo) * tanhf(cn);
            c[ci] = cn;
            hstore[ci] = hn;
        }
    }
}

// ---------------- final projection: out = r2 @ Wcomb^T + bcomb ----------------
// Block handles 32 consecutive rows of flattened [T*B] (row n = t*B + b), 128 threads.
__global__ void out_kernel(const float* __restrict__ r2, float* __restrict__ out)
{
    __shared__ float sw[NYv * 129];
    __shared__ float sr[32][129];
    int tid = threadIdx.x;
    for (int i = tid; i < NYv * Hv; i += 128) {
        int y = i >> 7, k = i & 127;
        sw[y * 129 + k] = g_wcomb[i];
    }
    size_t base = (size_t)blockIdx.x * 32 * Hv;
    for (int i = tid; i < 32 * Hv; i += 128) {
        int rr = i >> 7, kk = i & 127;
        sr[rr][kk] = r2[base + i];
    }
    __syncthreads();
    int r = tid >> 2, y = tid & 3;
    int n = blockIdx.x * 32 + r;
    int t = n >> 14;           // B = 2^14
    int b = n & (Bv - 1);
    float acc = g_bcomb[y];
#pragma unroll 4
    for (int k = 0; k < Hv; k++) acc += sw[y * 129 + k] * sr[r][k];
    out[((size_t)b * Tv + t) * NYv + y] = acc;
}

// ---------------- out_sfc = hN @ Wsfc^T + bsfc ----------------
__global__ void sfc_kernel(const float* __restrict__ Wsfc, const float* __restrict__ bsfc,
                           const float* __restrict__ hN, float* __restrict__ osfc)
{
    int i = blockIdx.x * blockDim.x + threadIdx.x;
    if (i >= Bv * NYSv) return;
    int b = i / 3, y = i - b * 3;
    const float* h = hN + (size_t)b * Hv;
    float acc = bsfc[y];
#pragma unroll 4
    for (int k = 0; k < Hv; k++) acc += Wsfc[y * Hv + k] * h[k];
    osfc[i] = acc;
}

// ---------------- launch ----------------
extern "C" void kernel_launch(void* const* d_in, const int* in_sizes, int n_in,
                              void* d_out, int out_size)
{
    const float* inputs_main = (const float*)d_in[0];
    const float* inputs_sfc  = (const float*)d_in[1];
    const float* mem0        = (const float*)d_in[2];
    const float* hx2         = (const float*)d_in[3];
    const float* cx2         = (const float*)d_in[4];
    const float* Ws1  = (const float*)d_in[5];
    const float* bs1  = (const float*)d_in[6];
    const float* Ws2  = (const float*)d_in[7];
    const float* bs2  = (const float*)d_in[8];
    const float* Wih1 = (const float*)d_in[9];
    const float* Whh1 = (const float*)d_in[10];
    const float* bih1 = (const float*)d_in[11];
    const float* bhh1 = (const float*)d_in[12];
    const float* Wih2 = (const float*)d_in[13];
    const float* Whh2 = (const float*)d_in[14];
    const float* bih2 = (const float*)d_in[15];
    const float* bhh2 = (const float*)d_in[16];
    const float* Wlat = (const float*)d_in[17];
    const float* blat = (const float*)d_in[18];
    const float* Wout = (const float*)d_in[19];
    const float* bout = (const float*)d_in[20];
    const float* Wsfc = (const float*)d_in[21];
    const float* bsfc = (const float*)d_in[22];
    float* out = (float*)d_out;

    float *r1, *r2, *h1, *c1, *c2, *b1, *b2;
    cudaGetSymbolAddress((void**)&r1, g_r1);
    cudaGetSymbolAddress((void**)&r2, g_r2);
    cudaGetSymbolAddress((void**)&h1, g_h1);
    cudaGetSymbolAddress((void**)&c1, g_c1);
    cudaGetSymbolAddress((void**)&c2, g_c2);
    cudaGetSymbolAddress((void**)&b1, g_b1);
    cudaGetSymbolAddress((void**)&b2, g_b2);

    init_kernel<<<(Bv * Hv + 255) / 256, 256>>>(inputs_sfc, Ws1, bs1, Ws2, bs2, cx2);
    prep_kernel<<<2, 256>>>(bih1, bhh1, bih2, bhh2, Wlat, blat, Wout, bout);

    dim3 grid(Bv / 128, 4);
    const size_t slab = (size_t)Bv * Hv;

    // Layer 1 (time-reversed input; outputs stored re-reversed so layer2 reads forward)
    for (int t = 0; t < Tv; t++) {
        const float* hi = (t == 0) ? h1 : (r1 + (size_t)(Tv - t) * slab);
        lstm_step<<<grid, 256>>>(inputs_main + (size_t)(Tv - 1 - t) * NXv, NXv, Tv * NXv,
                                 mem0 + (size_t)t * Hv, Tv * Hv,
                                 hi, c1,
                                 Wih1, NXv + Hv, Whh1, b1,
                                 r1 + (size_t)(Tv - 1 - t) * slab);
    }
    // Layer 2 (forward)
    for (int t = 0; t < Tv; t++) {
        const float* hi = (t == 0) ? hx2 : (r2 + (size_t)(t - 1) * slab);
        lstm_step<<<grid, 256>>>(nullptr, 0, 0,
                                 r1 + (size_t)t * slab, Hv,
                                 hi, c2,
                                 Wih2, Hv, Whh2, b2,
                                 r2 + (size_t)t * slab);
    }

    out_kernel<<<(Bv * Tv) / 32, 128>>>(r2, out);
    sfc_kernel<<<(Bv * NYSv + 255) / 256, 256>>>(Wsfc, bsfc,
                                                 r2 + (size_t)(Tv - 1) * slab,
                                                 out + (size_t)Bv * Tv * NYv);
}

// round 2
// speedup vs baseline: 1.1510x; 1.1510x over previous
#include <cuda_runtime.h>
#include <math.h>

#define Bv   16384
#define Tv   60
#define Hv   128
#define NXv  4
#define NYv  4
#define NYSv 3

#define PADA 133   // A_s row pad (odd*? -> conflict-free transpose stores, 133%32=5)
#define PADW 132   // ws row pad (multiple of 4 for LDS.128 alignment)
#define PADC 130   // c_s row pad (even for float2)

typedef unsigned long long ull;

// ---------------- scratch ----------------
__device__ float g_r1[(size_t)Tv * Bv * Hv];
__device__ float g_r2[(size_t)Tv * Bv * Hv];
__device__ float g_h1[Bv * Hv];
__device__ float g_c1[Bv * Hv];
__device__ float g_W1p[260 * 512];   // permuted+transposed [K=260][512]
__device__ float g_W2p[256 * 512];   // [K=256][512]
__device__ float g_b1p[512];
__device__ float g_b2p[512];
__device__ float g_wcomb[NYv * Hv];
__device__ float g_bcomb[NYv];

// ---------------- f32x2 helpers ----------------
__device__ __forceinline__ ull pk2(float x, float y) {
    ull r; asm("mov.b64 %0, {%1, %2};" : "=l"(r) : "f"(x), "f"(y)); return r;
}
__device__ __forceinline__ void upk2(ull v, float& x, float& y) {
    asm("mov.b64 {%0, %1}, %2;" : "=f"(x), "=f"(y) : "l"(v));
}
__device__ __forceinline__ void ffma2(ull& d, ull a, ull b) {
    asm("fma.rn.f32x2 %0, %1, %2, %0;" : "+l"(d) : "l"(a), "l"(b));
}

__device__ __forceinline__ float sigf(float x) {
    return __fdividef(1.0f, 1.0f + __expf(-x));
}
__device__ __forceinline__ float tanhf_(float x) {
    return __fdividef(2.0f, 1.0f + __expf(-2.0f * x)) - 1.0f;
}

// ---------------- init: h0/c0 for layer1 ----------------
__global__ void init_kernel(const float* __restrict__ sfc,
                            const float* __restrict__ Ws1, const float* __restrict__ bs1,
                            const float* __restrict__ Ws2, const float* __restrict__ bs2)
{
    int i = blockIdx.x * blockDim.x + threadIdx.x;
    if (i >= Bv * Hv) return;
    int b = i >> 7, j = i & 127;
    float s0 = sfc[b * 3 + 0], s1 = sfc[b * 3 + 1], s2 = sfc[b * 3 + 2];
    float a1 = bs1[j] + s0 * Ws1[j * 3 + 0] + s1 * Ws1[j * 3 + 1] + s2 * Ws1[j * 3 + 2];
    float a2 = bs2[j] + s0 * Ws2[j * 3 + 0] + s1 * Ws2[j * 3 + 1] + s2 * Ws2[j * 3 + 2];
    g_h1[i] = tanhf(a1);
    g_c1[i] = tanhf(a2);
}

// ---------------- prep: permuted weights/biases + folded output projection ----------------
// Column permutation within each 128-wide chunk ci: n = jj*4 + q  (jj: hidden-in-chunk, q: gate)
__global__ void prep_kernel(const float* __restrict__ Wih1, const float* __restrict__ Whh1,
                            const float* __restrict__ bih1, const float* __restrict__ bhh1,
                            const float* __restrict__ Wih2, const float* __restrict__ Whh2,
                            const float* __restrict__ bih2, const float* __restrict__ bhh2,
                            const float* __restrict__ Wlat, const float* __restrict__ blat,
                            const float* __restrict__ Wout, const float* __restrict__ bout)
{
    int idx = blockIdx.x * blockDim.x + threadIdx.x;
    const int N1 = 260 * 512, N2 = 256 * 512;
    if (idx < N1) {
        int k = idx >> 9, m = idx & 511;
        int ci = m >> 7, n = m & 127, q = n & 3, jj = n >> 2;
        int g = q * 128 + ci * 32 + jj;
        g_W1p[idx] = (k < 132) ? Wih1[g * 132 + k] : Whh1[g * 128 + (k - 132)];
        return;
    }
    int i2 = idx - N1;
    if (i2 < N2) {
        int k = i2 >> 9, m = i2 & 511;
        int ci = m >> 7, n = m & 127, q = n & 3, jj = n >> 2;
        int g = q * 128 + ci * 32 + jj;
        g_W2p[i2] = (k < 128) ? Wih2[g * 128 + k] : Whh2[g * 128 + (k - 128)];
        return;
    }
    int i3 = idx - N1 - N2;
    if (i3 < 512) {
        int ci = i3 >> 7, n = i3 & 127, q = n & 3, jj = n >> 2;
        int g = q * 128 + ci * 32 + jj;
        g_b1p[i3] = bih1[g] + bhh1[g];
        g_b2p[i3] = bih2[g] + bhh2[g];
        // folded output projection: Wcomb = Wout @ Wlat
        int y = i3 >> 7, j = i3 & 127;
        float acc = 0.0f;
        for (int k = 0; k < Hv; k++) acc += Wout[y * Hv + k] * Wlat[k * Hv + j];
        g_wcomb[i3] = acc;
        if (i3 < NYv) {
            float bb = bout[i3];
            for (int k = 0; k < Hv; k++) bb += Wout[i3 * Hv + k] * blat[k];
            g_bcomb[i3] = bb;
        }
    }
}

// ---------------- persistent fused 2-layer LSTM ----------------
// Grid: 128 CTAs x 256 threads. CTA owns batch rows [cta*128, cta*128+128).
// Runs layer1 (reverse time) then layer2 (forward), 60 steps each, locally.
// Inner GEMM: M=128 x N=128-chunk x K, f32x2 packed FMA, 8 rows x 4 col-pairs per thread.
__global__ __launch_bounds__(256, 1) void rnn_persist(
    const float* __restrict__ inputs_main,   // [B][T][4]
    const float* __restrict__ mem0,          // [B][T][128]
    const float* __restrict__ h1_0, const float* __restrict__ c1_0,
    const float* __restrict__ hx2,  const float* __restrict__ cx2,
    const float* __restrict__ W1p,  const float* __restrict__ b1p,
    const float* __restrict__ W2p,  const float* __restrict__ b2p,
    float* __restrict__ r1, float* __restrict__ r2)
{
    extern __shared__ float sm[];
    float* A_s    = sm;                           // [260][PADA] K-major activations
    float* c_s    = sm + 260 * PADA;              // [128][PADC]
    float* ws     = c_s + 128 * PADC;             // [32][PADW]  weight panel
    float* bias_s = ws + 32 * PADW;               // [512]

    const int tid = threadIdx.x;
    const int tx = tid & 15;
    const int ty = tid >> 4;
    const int b0 = blockIdx.x * 128;
    const size_t SLAB = (size_t)Bv * Hv;

    for (int layer = 0; layer < 2; ++layer) {
        const int KA   = layer ? 128 : 132;   // non-recurrent K
        const int KTOT = KA + 128;
        const int NPAN = (KTOT + 31) >> 5;
        const float* Wp = layer ? W2p : W1p;
        const float* bp = layer ? b2p : b1p;

        // load bias + initial c for this layer
        __syncthreads();
        for (int i = tid; i < 512; i += 256) bias_s[i] = bp[i];
        {
            const float* c0 = layer ? cx2 : c1_0;
            for (int i = tid; i < 128 * 128; i += 256) {
                int r = i >> 7, k = i & 127;
                c_s[r * PADC + k] = c0[(size_t)(b0 + r) * 128 + k];
            }
        }

        for (int t = 0; t < Tv; ++t) {
            const int ta = layer ? t : (Tv - 1 - t);   // actual time index
            const float* hsrc = (t == 0)
                ? (layer ? hx2 : h1_0)
                : (layer ? r2 + (size_t)(t - 1) * SLAB : r1 + (size_t)(ta + 1) * SLAB);
            float* hdst = layer ? r2 + (size_t)t * SLAB : r1 + (size_t)ta * SLAB;

            __syncthreads();   // protect A_s / ws from previous step's readers

            // ---- stage activations K-major into A_s ----
            if (layer == 0) {
                for (int i = tid; i < 512; i += 256) {           // x: k 0..3
                    int r = i >> 2, f = i & 3;
                    A_s[f * PADA + r] = inputs_main[(size_t)(b0 + r) * (Tv * NXv) + ta * NXv + f];
                }
                for (int i = tid; i < 128 * 128; i += 256) {     // mem0: k 4..131
                    int r = i >> 7, k = i & 127;
                    A_s[(4 + k) * PADA + r] = mem0[(size_t)(b0 + r) * (Tv * Hv) + t * Hv + k];
                }
            } else {
                for (int i = tid; i < 128 * 128; i += 256) {     // r1_t: k 0..127
                    int r = i >> 7, k = i & 127;
                    A_s[k * PADA + r] = r1[(size_t)t * SLAB + (size_t)(b0 + r) * 128 + k];
                }
            }
            for (int i = tid; i < 128 * 128; i += 256) {         // h: k KA..KA+127
                int r = i >> 7, k = i & 127;
                A_s[(KA + k) * PADA + r] = hsrc[(size_t)(b0 + r) * 128 + k];
            }

            // ---- 4 N-chunks of 128 permuted gate-columns ----
            for (int ci = 0; ci < 4; ++ci) {
                ull acc[8][4];
#pragma unroll
                for (int p = 0; p < 4; ++p) {
                    float2 bb = *(const float2*)&bias_s[ci * 128 + 8 * tx + 2 * p];
                    ull bv = pk2(bb.x, bb.y);
#pragma unroll
                    for (int i = 0; i < 8; i++) acc[i][p] = bv;
                }

                for (int p = 0; p < NPAN; ++p) {
                    const int kbase = p * 32;
                    const int pkk = (kbase + 32 <= KTOT) ? 32 : (KTOT - kbase);
                    __syncthreads();
                    const float* wsrc = Wp + (size_t)kbase * 512 + ci * 128;
                    for (int i = tid; i < (pkk << 7); i += 256) {
                        int kk = i >> 7, n = i & 127;
                        ws[kk * PADW + n] = wsrc[(size_t)kk * 512 + n];
                    }
                    __syncthreads();

                    const float* ap = A_s + kbase * PADA + ty * 8;
                    const float* wq = ws + 8 * tx;

#define GEMM_BODY(kk)                                                           \
    {                                                                           \
        float a_[8];                                                            \
        _Pragma("unroll")                                                       \
        for (int i = 0; i < 8; i++) a_[i] = ap[(kk) * PADA + i];                \
        float4 w0 = *(const float4*)(wq + (kk) * PADW);                         \
        float4 w1 = *(const float4*)(wq + (kk) * PADW + 4);                     \
        ull wq0 = pk2(w0.x, w0.y), wq1 = pk2(w0.z, w0.w);                       \
        ull wq2 = pk2(w1.x, w1.y), wq3 = pk2(w1.z, w1.w);                       \
        _Pragma("unroll")                                                       \
        for (int i = 0; i < 8; i++) {                                           \
            ull ad = pk2(a_[i], a_[i]);                                         \
            ffma2(acc[i][0], ad, wq0);                                          \
            ffma2(acc[i][1], ad, wq1);                                          \
            ffma2(acc[i][2], ad, wq2);                                          \
            ffma2(acc[i][3], ad, wq3);                                          \
        }                                                                       \
    }

                    if (pkk == 32) {
#pragma unroll 4
                        for (int kk = 0; kk < 32; ++kk) GEMM_BODY(kk)
                    } else {
                        for (int kk = 0; kk < pkk; ++kk) GEMM_BODY(kk)
                    }
#undef GEMM_BODY
                }

                // ---- cell epilogue: thread owns rows ty*8..+7, hiddens ci*32+2tx, +1 ----
                const int jg = ci * 32 + 2 * tx;
#pragma unroll
                for (int i = 0; i < 8; i++) {
                    const int row = ty * 8 + i;
                    float zi0, zf0, zg0, zo0, zi1, zf1, zg1, zo1;
                    upk2(acc[i][0], zi0, zf0);
                    upk2(acc[i][1], zg0, zo0);
                    upk2(acc[i][2], zi1, zf1);
                    upk2(acc[i][3], zg1, zo1);
                    float2 cc = *(float2*)&c_s[row * PADC + jg];
                    float c0n = sigf(zf0) * cc.x + sigf(zi0) * tanhf_(zg0);
                    float c1n = sigf(zf1) * cc.y + sigf(zi1) * tanhf_(zg1);
                    float h0 = sigf(zo0) * tanhf_(c0n);
                    float h1 = sigf(zo1) * tanhf_(c1n);
                    *(float2*)&c_s[row * PADC + jg] = make_float2(c0n, c1n);
                    *(float2*)&hdst[(size_t)(b0 + row) * 128 + jg] = make_float2(h0, h1);
                }
            }
        }
    }
}

// ---------------- final projection: out = r2 @ Wcomb^T + bcomb ----------------
__global__ void out_kernel(const float* __restrict__ r2, float* __restrict__ out)
{
    __shared__ float sw[NYv * 129];
    __shared__ float sr[32][129];
    int tid = threadIdx.x;
    for (int i = tid; i < NYv * Hv; i += 128) {
        int y = i >> 7, k = i & 127;
        sw[y * 129 + k] = g_wcomb[i];
    }
    size_t base = (size_t)blockIdx.x * 32 * Hv;
    for (int i = tid; i < 32 * Hv; i += 128) {
        int rr = i >> 7, kk = i & 127;
        sr[rr][kk] = r2[base + i];
    }
    __syncthreads();
    int r = tid >> 2, y = tid & 3;
    int n = blockIdx.x * 32 + r;
    int t = n >> 14;
    int b = n & (Bv - 1);
    float acc = g_bcomb[y];
#pragma unroll 4
    for (int k = 0; k < Hv; k++) acc += sw[y * 129 + k] * sr[r][k];
    out[((size_t)b * Tv + t) * NYv + y] = acc;
}

// ---------------- out_sfc = hN @ Wsfc^T + bsfc ----------------
__global__ void sfc_kernel(const float* __restrict__ Wsfc, const float* __restrict__ bsfc,
                           const float* __restrict__ hN, float* __restrict__ osfc)
{
    int i = blockIdx.x * blockDim.x + threadIdx.x;
    if (i >= Bv * NYSv) return;
    int b = i / 3, y = i - b * 3;
    const float* h = hN + (size_t)b * Hv;
    float acc = bsfc[y];
#pragma unroll 4
    for (int k = 0; k < Hv; k++) acc += Wsfc[y * Hv + k] * h[k];
    osfc[i] = acc;
}

// ---------------- launch ----------------
extern "C" void kernel_launch(void* const* d_in, const int* in_sizes, int n_in,
                              void* d_out, int out_size)
{
    const float* inputs_main = (const float*)d_in[0];
    const float* inputs_sfc  = (const float*)d_in[1];
    const float* mem0        = (const float*)d_in[2];
    const float* hx2         = (const float*)d_in[3];
    const float* cx2         = (const float*)d_in[4];
    const float* Ws1  = (const float*)d_in[5];
    const float* bs1  = (const float*)d_in[6];
    const float* Ws2  = (const float*)d_in[7];
    const float* bs2  = (const float*)d_in[8];
    const float* Wih1 = (const float*)d_in[9];
    const float* Whh1 = (const float*)d_in[10];
    const float* bih1 = (const float*)d_in[11];
    const float* bhh1 = (const float*)d_in[12];
    const float* Wih2 = (const float*)d_in[13];
    const float* Whh2 = (const float*)d_in[14];
    const float* bih2 = (const float*)d_in[15];
    const float* bhh2 = (const float*)d_in[16];
    const float* Wlat = (const float*)d_in[17];
    const float* blat = (const float*)d_in[18];
    const float* Wout = (const float*)d_in[19];
    const float* bout = (const float*)d_in[20];
    const float* Wsfc = (const float*)d_in[21];
    const float* bsfc = (const float*)d_in[22];
    float* out = (float*)d_out;

    float *r1, *r2, *h1, *c1, *W1p, *W2p, *b1p, *b2p;
    cudaGetSymbolAddress((void**)&r1, g_r1);
    cudaGetSymbolAddress((void**)&r2, g_r2);
    cudaGetSymbolAddress((void**)&h1, g_h1);
    cudaGetSymbolAddress((void**)&c1, g_c1);
    cudaGetSymbolAddress((void**)&W1p, g_W1p);
    cudaGetSymbolAddress((void**)&W2p, g_W2p);
    cudaGetSymbolAddress((void**)&b1p, g_b1p);
    cudaGetSymbolAddress((void**)&b2p, g_b2p);

    const int SMEM_BYTES = (260 * PADA + 128 * PADC + 32 * PADW + 512) * 4;
    cudaFuncSetAttribute(rnn_persist, cudaFuncAttributeMaxDynamicSharedMemorySize, SMEM_BYTES);

    init_kernel<<<(Bv * Hv + 255) / 256, 256>>>(inputs_sfc, Ws1, bs1, Ws2, bs2);

    const int PREP_N = 260 * 512 + 256 * 512 + 512;
    prep_kernel<<<(PREP_N + 255) / 256, 256>>>(Wih1, Whh1, bih1, bhh1,
                                               Wih2, Whh2, bih2, bhh2,
                                               Wlat, blat, Wout, bout);

    rnn_persist<<<128, 256, SMEM_BYTES>>>(inputs_main, mem0, h1, c1, hx2, cx2,
                                          W1p, b1p, W2p, b2p, r1, r2);

    out_kernel<<<(Bv * Tv) / 32, 128>>>(r2, out);
    sfc_kernel<<<(Bv * NYSv + 255) / 256, 256>>>(Wsfc, bsfc,
                                                 r2 + (size_t)(Tv - 1) * Bv * Hv,
                                                 out + (size_t)Bv * Tv * NYv);
}

// round 3
// speedup vs baseline: 1.1524x; 1.0012x over previous
#include <cuda_runtime.h>
#include <math.h>

#define Bv   16384
#define Tv   60
#define Hv   128
#define NXv  4
#define NYv  4
#define NYSv 3

#define PADA 133   // A_s row pad (odd*? -> conflict-free transpose stores, 133%32=5)
#define PADW 132   // ws row pad (multiple of 4 for LDS.128 alignment)
#define PADC 130   // c_s row pad (even for float2)

typedef unsigned long long ull;

// ---------------- scratch ----------------
__device__ float g_r1[(size_t)Tv * Bv * Hv];
__device__ float g_r2[(size_t)Tv * Bv * Hv];
__device__ float g_h1[Bv * Hv];
__device__ float g_c1[Bv * Hv];
__device__ float g_W1p[260 * 512];   // permuted+transposed [K=260][512]
__device__ float g_W2p[256 * 512];   // [K=256][512]
__device__ float g_b1p[512];
__device__ float g_b2p[512];
__device__ float g_wcomb[NYv * Hv];
__device__ float g_bcomb[NYv];

// ---------------- f32x2 helpers ----------------
__device__ __forceinline__ ull pk2(float x, float y) {
    ull r; asm("mov.b64 %0, {%1, %2};" : "=l"(r) : "f"(x), "f"(y)); return r;
}
__device__ __forceinline__ void upk2(ull v, float& x, float& y) {
    asm("mov.b64 {%0, %1}, %2;" : "=f"(x), "=f"(y) : "l"(v));
}
__device__ __forceinline__ void ffma2(ull& d, ull a, ull b) {
    asm("fma.rn.f32x2 %0, %1, %2, %0;" : "+l"(d) : "l"(a), "l"(b));
}

__device__ __forceinline__ float sigf(float x) {
    return __fdividef(1.0f, 1.0f + __expf(-x));
}
__device__ __forceinline__ float tanhf_(float x) {
    return __fdividef(2.0f, 1.0f + __expf(-2.0f * x)) - 1.0f;
}

// ---------------- init: h0/c0 for layer1 ----------------
__global__ void init_kernel(const float* __restrict__ sfc,
                            const float* __restrict__ Ws1, const float* __restrict__ bs1,
                            const float* __restrict__ Ws2, const float* __restrict__ bs2)
{
    int i = blockIdx.x * blockDim.x + threadIdx.x;
    if (i >= Bv * Hv) return;
    int b = i >> 7, j = i & 127;
    float s0 = sfc[b * 3 + 0], s1 = sfc[b * 3 + 1], s2 = sfc[b * 3 + 2];
    float a1 = bs1[j] + s0 * Ws1[j * 3 + 0] + s1 * Ws1[j * 3 + 1] + s2 * Ws1[j * 3 + 2];
    float a2 = bs2[j] + s0 * Ws2[j * 3 + 0] + s1 * Ws2[j * 3 + 1] + s2 * Ws2[j * 3 + 2];
    g_h1[i] = tanhf(a1);
    g_c1[i] = tanhf(a2);
}

// ---------------- prep: permuted weights/biases + folded output projection ----------------
// Column permutation within each 128-wide chunk ci: n = jj*4 + q  (jj: hidden-in-chunk, q: gate)
__global__ void prep_kernel(const float* __restrict__ Wih1, const float* __restrict__ Whh1,
                            const float* __restrict__ bih1, const float* __restrict__ bhh1,
                            const float* __restrict__ Wih2, const float* __restrict__ Whh2,
                            const float* __restrict__ bih2, const float* __restrict__ bhh2,
                            const float* __restrict__ Wlat, const float* __restrict__ blat,
                            const float* __restrict__ Wout, const float* __restrict__ bout)
{
    int idx = blockIdx.x * blockDim.x + threadIdx.x;
    const int N1 = 260 * 512, N2 = 256 * 512;
    if (idx < N1) {
        int k = idx >> 9, m = idx & 511;
        int ci = m >> 7, n = m & 127, q = n & 3, jj = n >> 2;
        int g = q * 128 + ci * 32 + jj;
        g_W1p[idx] = (k < 132) ? Wih1[g * 132 + k] : Whh1[g * 128 + (k - 132)];
        return;
    }
    int i2 = idx - N1;
    if (i2 < N2) {
        int k = i2 >> 9, m = i2 & 511;
        int ci = m >> 7, n = m & 127, q = n & 3, jj = n >> 2;
        int g = q * 128 + ci * 32 + jj;
        g_W2p[i2] = (k < 128) ? Wih2[g * 128 + k] : Whh2[g * 128 + (k - 128)];
        return;
    }
    int i3 = idx - N1 - N2;
    if (i3 < 512) {
        int ci = i3 >> 7, n = i3 & 127, q = n & 3, jj = n >> 2;
        int g = q * 128 + ci * 32 + jj;
        g_b1p[i3] = bih1[g] + bhh1[g];
        g_b2p[i3] = bih2[g] + bhh2[g];
        // folded output projection: Wcomb = Wout @ Wlat
        int y = i3 >> 7, j = i3 & 127;
        float acc = 0.0f;
        for (int k = 0; k < Hv; k++) acc += Wout[y * Hv + k] * Wlat[k * Hv + j];
        g_wcomb[i3] = acc;
        if (i3 < NYv) {
            float bb = bout[i3];
            for (int k = 0; k < Hv; k++) bb += Wout[i3 * Hv + k] * blat[k];
            g_bcomb[i3] = bb;
        }
    }
}

// ---------------- persistent fused 2-layer LSTM ----------------
// Grid: 128 CTAs x 256 threads. CTA owns batch rows [cta*128, cta*128+128).
// Runs layer1 (reverse time) then layer2 (forward), 60 steps each, locally.
// Inner GEMM: M=128 x N=128-chunk x K, f32x2 packed FMA, 8 rows x 4 col-pairs per thread.
__global__ __launch_bounds__(256, 1) void rnn_persist(
    const float* __restrict__ inputs_main,   // [B][T][4]
    const float* __restrict__ mem0,          // [B][T][128]
    const float* __restrict__ h1_0, const float* __restrict__ c1_0,
    const float* __restrict__ hx2,  const float* __restrict__ cx2,
    const float* __restrict__ W1p,  const float* __restrict__ b1p,
    const float* __restrict__ W2p,  const float* __restrict__ b2p,
    float* __restrict__ r1, float* __restrict__ r2)
{
    extern __shared__ float sm[];
    float* A_s    = sm;                           // [260][PADA] K-major activations
    float* c_s    = sm + 260 * PADA;              // [128][PADC]
    float* ws     = c_s + 128 * PADC;             // [32][PADW]  weight panel
    float* bias_s = ws + 32 * PADW;               // [512]

    const int tid = threadIdx.x;
    const int tx = tid & 15;
    const int ty = tid >> 4;
    const int b0 = blockIdx.x * 128;
    const size_t SLAB = (size_t)Bv * Hv;

    for (int layer = 0; layer < 2; ++layer) {
        const int KA   = layer ? 128 : 132;   // non-recurrent K
        const int KTOT = KA + 128;
        const int NPAN = (KTOT + 31) >> 5;
        const float* Wp = layer ? W2p : W1p;
        const float* bp = layer ? b2p : b1p;

        // load bias + initial c for this layer
        __syncthreads();
        for (int i = tid; i < 512; i += 256) bias_s[i] = bp[i];
        {
            const float* c0 = layer ? cx2 : c1_0;
            for (int i = tid; i < 128 * 128; i += 256) {
                int r = i >> 7, k = i & 127;
                c_s[r * PADC + k] = c0[(size_t)(b0 + r) * 128 + k];
            }
        }

        for (int t = 0; t < Tv; ++t) {
            const int ta = layer ? t : (Tv - 1 - t);   // actual time index
            const float* hsrc = (t == 0)
                ? (layer ? hx2 : h1_0)
                : (layer ? r2 + (size_t)(t - 1) * SLAB : r1 + (size_t)(ta + 1) * SLAB);
            float* hdst = layer ? r2 + (size_t)t * SLAB : r1 + (size_t)ta * SLAB;

            __syncthreads();   // protect A_s / ws from previous step's readers

            // ---- stage activations K-major into A_s ----
            if (layer == 0) {
                for (int i = tid; i < 512; i += 256) {           // x: k 0..3
                    int r = i >> 2, f = i & 3;
                    A_s[f * PADA + r] = inputs_main[(size_t)(b0 + r) * (Tv * NXv) + ta * NXv + f];
                }
                for (int i = tid; i < 128 * 128; i += 256) {     // mem0: k 4..131
                    int r = i >> 7, k = i & 127;
                    A_s[(4 + k) * PADA + r] = mem0[(size_t)(b0 + r) * (Tv * Hv) + t * Hv + k];
                }
            } else {
                for (int i = tid; i < 128 * 128; i += 256) {     // r1_t: k 0..127
                    int r = i >> 7, k = i & 127;
                    A_s[k * PADA + r] = r1[(size_t)t * SLAB + (size_t)(b0 + r) * 128 + k];
                }
            }
            for (int i = tid; i < 128 * 128; i += 256) {         // h: k KA..KA+127
                int r = i >> 7, k = i & 127;
                A_s[(KA + k) * PADA + r] = hsrc[(size_t)(b0 + r) * 128 + k];
            }

            // ---- 4 N-chunks of 128 permuted gate-columns ----
            for (int ci = 0; ci < 4; ++ci) {
                ull acc[8][4];
#pragma unroll
                for (int p = 0; p < 4; ++p) {
                    float2 bb = *(const float2*)&bias_s[ci * 128 + 8 * tx + 2 * p];
                    ull bv = pk2(bb.x, bb.y);
#pragma unroll
                    for (int i = 0; i < 8; i++) acc[i][p] = bv;
                }

                for (int p = 0; p < NPAN; ++p) {
                    const int kbase = p * 32;
                    const int pkk = (kbase + 32 <= KTOT) ? 32 : (KTOT - kbase);
                    __syncthreads();
                    const float* wsrc = Wp + (size_t)kbase * 512 + ci * 128;
                    for (int i = tid; i < (pkk << 7); i += 256) {
                        int kk = i >> 7, n = i & 127;
                        ws[kk * PADW + n] = wsrc[(size_t)kk * 512 + n];
                    }
                    __syncthreads();

                    const float* ap = A_s + kbase * PADA + ty * 8;
                    const float* wq = ws + 8 * tx;

#define GEMM_BODY(kk)                                                           \
    {                                                                           \
        float a_[8];                                                            \
        _Pragma("unroll")                                                       \
        for (int i = 0; i < 8; i++) a_[i] = ap[(kk) * PADA + i];                \
        float4 w0 = *(const float4*)(wq + (kk) * PADW);                         \
        float4 w1 = *(const float4*)(wq + (kk) * PADW + 4);                     \
        ull wq0 = pk2(w0.x, w0.y), wq1 = pk2(w0.z, w0.w);                       \
        ull wq2 = pk2(w1.x, w1.y), wq3 = pk2(w1.z, w1.w);                       \
        _Pragma("unroll")                                                       \
        for (int i = 0; i < 8; i++) {                                           \
            ull ad = pk2(a_[i], a_[i]);                                         \
            ffma2(acc[i][0], ad, wq0);                                          \
            ffma2(acc[i][1], ad, wq1);                                          \
            ffma2(acc[i][2], ad, wq2);                                          \
            ffma2(acc[i][3], ad, wq3);                                          \
        }                                                                       \
    }

                    if (pkk == 32) {
#pragma unroll 4
                        for (int kk = 0; kk < 32; ++kk) GEMM_BODY(kk)
                    } else {
                        for (int kk = 0; kk < pkk; ++kk) GEMM_BODY(kk)
                    }
#undef GEMM_BODY
                }

                // ---- cell epilogue: thread owns rows ty*8..+7, hiddens ci*32+2tx, +1 ----
                const int jg = ci * 32 + 2 * tx;
#pragma unroll
                for (int i = 0; i < 8; i++) {
                    const int row = ty * 8 + i;
                    float zi0, zf0, zg0, zo0, zi1, zf1, zg1, zo1;
                    upk2(acc[i][0], zi0, zf0);
                    upk2(acc[i][1], zg0, zo0);
                    upk2(acc[i][2], zi1, zf1);
                    upk2(acc[i][3], zg1, zo1);
                    float2 cc = *(float2*)&c_s[row * PADC + jg];
                    float c0n = sigf(zf0) * cc.x + sigf(zi0) * tanhf_(zg0);
                    float c1n = sigf(zf1) * cc.y + sigf(zi1) * tanhf_(zg1);
                    float h0 = sigf(zo0) * tanhf_(c0n);
                    float h1 = sigf(zo1) * tanhf_(c1n);
                    *(float2*)&c_s[row * PADC + jg] = make_float2(c0n, c1n);
                    *(float2*)&hdst[(size_t)(b0 + row) * 128 + jg] = make_float2(h0, h1);
                }
            }
        }
    }
}

// ---------------- final projection: out = r2 @ Wcomb^T + bcomb ----------------
__global__ void out_kernel(const float* __restrict__ r2, float* __restrict__ out)
{
    __shared__ float sw[NYv * 129];
    __shared__ float sr[32][129];
    int tid = threadIdx.x;
    for (int i = tid; i < NYv * Hv; i += 128) {
        int y = i >> 7, k = i & 127;
        sw[y * 129 + k] = g_wcomb[i];
    }
    size_t base = (size_t)blockIdx.x * 32 * Hv;
    for (int i = tid; i < 32 * Hv; i += 128) {
        int rr = i >> 7, kk = i & 127;
        sr[rr][kk] = r2[base + i];
    }
    __syncthreads();
    int r = tid >> 2, y = tid & 3;
    int n = blockIdx.x * 32 + r;
    int t = n >> 14;
    int b = n & (Bv - 1);
    float acc = g_bcomb[y];
#pragma unroll 4
    for (int k = 0; k < Hv; k++) acc += sw[y * 129 + k] * sr[r][k];
    out[((size_t)b * Tv + t) * NYv + y] = acc;
}

// ---------------- out_sfc = hN @ Wsfc^T + bsfc ----------------
__global__ void sfc_kernel(const float* __restrict__ Wsfc, const float* __restrict__ bsfc,
                           const float* __restrict__ hN, float* __restrict__ osfc)
{
    int i = blockIdx.x * blockDim.x + threadIdx.x;
    if (i >= Bv * NYSv) return;
    int b = i / 3, y = i - b * 3;
    const float* h = hN + (size_t)b * Hv;
    float acc = bsfc[y];
#pragma unroll 4
    for (int k = 0; k < Hv; k++) acc += Wsfc[y * Hv + k] * h[k];
    osfc[i] = acc;
}

// ---------------- launch ----------------
extern "C" void kernel_launch(void* const* d_in, const int* in_sizes, int n_in,
                              void* d_out, int out_size)
{
    const float* inputs_main = (const float*)d_in[0];
    const float* inputs_sfc  = (const float*)d_in[1];
    const float* mem0        = (const float*)d_in[2];
    const float* hx2         = (const float*)d_in[3];
    const float* cx2         = (const float*)d_in[4];
    const float* Ws1  = (const float*)d_in[5];
    const float* bs1  = (const float*)d_in[6];
    const float* Ws2  = (const float*)d_in[7];
    const float* bs2  = (const float*)d_in[8];
    const float* Wih1 = (const float*)d_in[9];
    const float* Whh1 = (const float*)d_in[10];
    const float* bih1 = (const float*)d_in[11];
    const float* bhh1 = (const float*)d_in[12];
    const float* Wih2 = (const float*)d_in[13];
    const float* Whh2 = (const float*)d_in[14];
    const float* bih2 = (const float*)d_in[15];
    const float* bhh2 = (const float*)d_in[16];
    const float* Wlat = (const float*)d_in[17];
    const float* blat = (const float*)d_in[18];
    const float* Wout = (const float*)d_in[19];
    const float* bout = (const float*)d_in[20];
    const float* Wsfc = (const float*)d_in[21];
    const float* bsfc = (const float*)d_in[22];
    float* out = (float*)d_out;

    float *r1, *r2, *h1, *c1, *W1p, *W2p, *b1p, *b2p;
    cudaGetSymbolAddress((void**)&r1, g_r1);
    cudaGetSymbolAddress((void**)&r2, g_r2);
    cudaGetSymbolAddress((void**)&h1, g_h1);
    cudaGetSymbolAddress((void**)&c1, g_c1);
    cudaGetSymbolAddress((void**)&W1p, g_W1p);
    cudaGetSymbolAddress((void**)&W2p, g_W2p);
    cudaGetSymbolAddress((void**)&b1p, g_b1p);
    cudaGetSymbolAddress((void**)&b2p, g_b2p);

    const int SMEM_BYTES = (260 * PADA + 128 * PADC + 32 * PADW + 512) * 4;
    cudaFuncSetAttribute(rnn_persist, cudaFuncAttributeMaxDynamicSharedMemorySize, SMEM_BYTES);

    init_kernel<<<(Bv * Hv + 255) / 256, 256>>>(inputs_sfc, Ws1, bs1, Ws2, bs2);

    const int PREP_N = 260 * 512 + 256 * 512 + 512;
    prep_kernel<<<(PREP_N + 255) / 256, 256>>>(Wih1, Whh1, bih1, bhh1,
                                               Wih2, Whh2, bih2, bhh2,
                                               Wlat, blat, Wout, bout);

    rnn_persist<<<128, 256, SMEM_BYTES>>>(inputs_main, mem0, h1, c1, hx2, cx2,
                                          W1p, b1p, W2p, b2p, r1, r2);

    out_kernel<<<(Bv * Tv) / 32, 128>>>(r2, out);
    sfc_kernel<<<(Bv * NYSv + 255) / 256, 256>>>(Wsfc, bsfc,
                                                 r2 + (size_t)(Tv - 1) * Bv * Hv,
                                                 out + (size_t)Bv * Tv * NYv);
}